// round 13
// baseline (speedup 1.0000x reference)
#include <cuda_runtime.h>

#define NHEAD  8
#define SEQ    4096
#define DH     8
#define PAIRS  2048              // t-pairs per head
#define QPAIRS 512               // t-pairs per quarter (split-KV x4)
#define NSPLIT 4
#define CAP    10                // deferred-entry slots per (thread,row)
#define WIN    20.0f             // window: dropped terms < 4096*e^-20 ~ 8e-6
#define NROWS  (NHEAD * SEQ)

// ---------------- __device__ scratch (no allocations allowed) ----------------
// Keys packed per quarter, INTERLEAVED inside each quarter: pair p (0..2047) of
// head g: quarter = p>>9, ph = p & 511,
//   dst = g*2048 + quarter*512 + (ph & 127)*4 + (ph >> 7)
// so quad lane q (owning 128 pairs of the quarter) reads zs[p*4+q]: 64 B
// contiguous per quad + row broadcast -> conflict-free.
//  zA word: (zx_t, zx_t1, zy_t, zy_t1),  zB word: (zz_t, zz_t1, zw_t, zw_t1)
// where z_t = SCALE * ( Wq^T Wk x2_t , bq . Wk x2_t ).
__device__ float4 g_zA[NHEAD * PAIRS];
__device__ float4 g_zB[NHEAD * PAIRS];
__device__ float  g_v [NHEAD * SEQ * DH];    // v[g][t][h] = Wv x1 + bv
// Per (quarter, row) softmax partials: acc[8], m, l  (10 floats)
__device__ float  g_part[NSPLIT * NROWS * 10];

// ---------------------------------------------------------------------------
// Packed f32x2 helpers
// ---------------------------------------------------------------------------
__device__ __forceinline__ unsigned long long fma2(unsigned long long a,
                                                   unsigned long long b,
                                                   unsigned long long c) {
    unsigned long long d;
    asm("fma.rn.f32x2 %0, %1, %2, %3;" : "=l"(d) : "l"(a), "l"(b), "l"(c));
    return d;
}
__device__ __forceinline__ unsigned long long pack2(float x, float y) {
    unsigned long long r;
    asm("mov.b64 %0, {%1, %2};" : "=l"(r) : "f"(x), "f"(y));
    return r;
}
__device__ __forceinline__ void unpack2(unsigned long long v, float& x, float& y) {
    asm("mov.b64 {%0, %1}, %2;" : "=f"(x), "=f"(y) : "l"(v));
}

// ---------------------------------------------------------------------------
// Precompute: one thread per t (32768 threads); pair packing via shfl.
// ---------------------------------------------------------------------------
__global__ void precompute_kernel(const float* __restrict__ x1,
                                  const float* __restrict__ x2,
                                  const float* __restrict__ Wq,
                                  const float* __restrict__ bq,
                                  const float* __restrict__ Wk,
                                  const float* __restrict__ Wv,
                                  const float* __restrict__ bv) {
    const int i = blockIdx.x * blockDim.x + threadIdx.x;  // i = g*SEQ + t
    if (i >= NHEAD * SEQ) return;
    const int g = i >> 12;
    const int t = i & (SEQ - 1);

    const float SCALEF = 1448.1546878700492f;  // 2^10.5

    float X1[3], X2[3];
#pragma unroll
    for (int j = 0; j < 3; j++) { X1[j] = x1[i * 3 + j]; X2[j] = x2[i * 3 + j]; }

    float y0 = 0.f, y1 = 0.f, y2 = 0.f, w = 0.f;
#pragma unroll
    for (int h = 0; h < 8; h++) {
        float u = fmaf(Wk[h * 3 + 0], X2[0],
                  fmaf(Wk[h * 3 + 1], X2[1], Wk[h * 3 + 2] * X2[2]));
        y0 = fmaf(Wq[h * 3 + 0], u, y0);
        y1 = fmaf(Wq[h * 3 + 1], u, y1);
        y2 = fmaf(Wq[h * 3 + 2], u, y2);
        w  = fmaf(bq[h], u, w);
    }
    y0 *= SCALEF; y1 *= SCALEF; y2 *= SCALEF; w *= SCALEF;

#pragma unroll
    for (int h = 0; h < 8; h++) {
        g_v[(size_t)i * 8 + h] =
            fmaf(Wv[h * 3 + 0], X1[0], fmaf(Wv[h * 3 + 1], X1[1],
            fmaf(Wv[h * 3 + 2], X1[2], bv[h])));
    }

    const float py0 = __shfl_xor_sync(0xffffffffu, y0, 1);
    const float py1 = __shfl_xor_sync(0xffffffffu, y1, 1);
    const float py2 = __shfl_xor_sync(0xffffffffu, y2, 1);
    const float pw  = __shfl_xor_sync(0xffffffffu, w,  1);
    if (!(t & 1)) {
        const int p  = t >> 1;
        const int ph = p & (QPAIRS - 1);
        const int dst = g * PAIRS + (p >> 9) * QPAIRS + ((ph & 127) << 2) + (ph >> 7);
        g_zA[dst] = make_float4(y0, py0, y1, py1);
        g_zB[dst] = make_float4(y2, py2, w, pw);
    }
}

// ---------------------------------------------------------------------------
// Threefry2x32, partitionable mode: word(i) = x0^x1 of counter (0, i),
// key (0, 42). keep <=> MSB == 0.
// ---------------------------------------------------------------------------
__device__ __forceinline__ unsigned rotl32(unsigned x, int r) {
    return __funnelshift_l(x, x, r);
}
__device__ __forceinline__ unsigned threefry_word(unsigned idx) {
    const unsigned K1 = 42u;
    const unsigned K2 = 0x1BD11BF0u;
    unsigned x0 = 0u;
    unsigned x1 = idx + K1;
#define TF_R(r)  { x0 += x1; x1 = rotl32(x1, r); x1 ^= x0; }
#define TF_G(a,b,c,d,j0,j1) TF_R(a) TF_R(b) TF_R(c) TF_R(d) x0 += (j0); x1 += (j1);
    TF_G(13, 15, 26,  6, K1,       K2 + 1u)
    TF_G(17, 29, 16, 24, K2,       0u + 2u)
    TF_G(13, 15, 26,  6, 0u,       K1 + 3u)
    TF_G(17, 29, 16, 24, K1,       K2 + 4u)
    TF_G(13, 15, 26,  6, K2,       0u + 5u)
#undef TF_G
#undef TF_R
    return x0 ^ x1;
}

// Exact fp32 re-score of lane-local t (0..255) from smem (same FMA chain as
// the scan -> bit-identical values).
__device__ __forceinline__ float score_at(const float4* __restrict__ zs, int q,
                                          int tloc, float a, float b, float c) {
    const int idx = ((tloc >> 1) << 2) + q;
    const float4 A = zs[idx];
    const float4 B = zs[QPAIRS + idx];
    const bool odd = (tloc & 1);
    const float zx = odd ? A.y : A.x;
    const float zy = odd ? A.w : A.z;
    const float zz = odd ? B.y : B.x;
    const float zw = odd ? B.w : B.z;
    return fmaf(a, zx, fmaf(b, zy, fmaf(c, zz, zw)));
}

__device__ __forceinline__ void emit32(unsigned short* buf, int& cnt,
                                       const float4* __restrict__ zs, int q,
                                       float a, float b, float c,
                                       float m, int tl) {
    if (cnt == CAP) {                       // prune entries below current window
        int k = 0;
        for (int i = 0; i < CAP; i++) {
            const int t2 = buf[i];
            if (score_at(zs, q, t2, a, b, c) > m - WIN)
                buf[k++] = (unsigned short)t2;
        }
        cnt = k;
        if (cnt == CAP) cnt = CAP - 1;      // ~impossible; keep newest
    }
    buf[cnt++] = (unsigned short)tl;
}

// Phase 2 + quad merge; writes (acc[8], m, l) partial for (quarter, row).
__device__ __forceinline__ void finalize_row(const float4* __restrict__ zs,
                                             const unsigned short* buf, int cnt,
                                             float m, int q, int g, int quarter,
                                             int row, float a, float b, float c) {
    const int tbase = quarter * 1024 + (q << 8);       // global t of lane's range
    const float* vg = g_v + ((size_t)g * SEQ + tbase) * DH;
    const unsigned rowbase = ((unsigned)row << 12) + (unsigned)tbase;
    const float M = m;
    float l = 0.f;
    float acc0 = 0.f, acc1 = 0.f, acc2 = 0.f, acc3 = 0.f;
    float acc4 = 0.f, acc5 = 0.f, acc6 = 0.f, acc7 = 0.f;
    for (int i = 0; i < cnt; i++) {
        const int tloc = buf[i];
        const float sc = score_at(zs, q, tloc, a, b, c);
        if (sc > M - WIN) {
            const float e = __expf(sc - M);
            l += e;                                    // denominator: mask-free
            const unsigned w = threefry_word(rowbase + (unsigned)tloc);
            if (!(w & 0x80000000u)) {                  // keep (u < 0.5)
                const float4* vp =
                    reinterpret_cast<const float4*>(vg + (size_t)tloc * DH);
                const float4 va = vp[0];
                const float4 vb = vp[1];
                acc0 = fmaf(e, va.x, acc0);
                acc1 = fmaf(e, va.y, acc1);
                acc2 = fmaf(e, va.z, acc2);
                acc3 = fmaf(e, va.w, acc3);
                acc4 = fmaf(e, vb.x, acc4);
                acc5 = fmaf(e, vb.y, acc5);
                acc6 = fmaf(e, vb.z, acc6);
                acc7 = fmaf(e, vb.w, acc7);
            }
        }
    }
    // quad merge (lanes xor 1, 2 share a row)
    float Mq = M;
    Mq = fmaxf(Mq, __shfl_xor_sync(0xffffffffu, Mq, 1));
    Mq = fmaxf(Mq, __shfl_xor_sync(0xffffffffu, Mq, 2));
    const float f = __expf(M - Mq);
    l *= f;
    acc0 *= f; acc1 *= f; acc2 *= f; acc3 *= f;
    acc4 *= f; acc5 *= f; acc6 *= f; acc7 *= f;
#pragma unroll
    for (int d = 1; d <= 2; d <<= 1) {
        l    += __shfl_xor_sync(0xffffffffu, l,    d);
        acc0 += __shfl_xor_sync(0xffffffffu, acc0, d);
        acc1 += __shfl_xor_sync(0xffffffffu, acc1, d);
        acc2 += __shfl_xor_sync(0xffffffffu, acc2, d);
        acc3 += __shfl_xor_sync(0xffffffffu, acc3, d);
        acc4 += __shfl_xor_sync(0xffffffffu, acc4, d);
        acc5 += __shfl_xor_sync(0xffffffffu, acc5, d);
        acc6 += __shfl_xor_sync(0xffffffffu, acc6, d);
        acc7 += __shfl_xor_sync(0xffffffffu, acc7, d);
    }
    float* part = g_part + ((size_t)quarter * NROWS + row) * 10;
    const float oc[8] = {acc0, acc1, acc2, acc3, acc4, acc5, acc6, acc7};
    part[2 * q]     = oc[2 * q];
    part[2 * q + 1] = oc[2 * q + 1];
    if (q == 0) { part[8] = Mq; part[9] = l; }
}

// ---------------------------------------------------------------------------
// Main kernel. Grid (SEQ/256, NHEAD, 4) = (16, 8, 4); block = 256 threads:
// 64 row-slots x quad(4). Each thread owns FOUR rows (s0, +64, +128, +192),
// so each LDS.128 of z feeds 4 rows of scores. blockIdx.z = t-quarter; quad
// lane q scans the quarter's pairs [q*128,(q+1)*128) (256 t's, 32 iters).
// smem = 16 KB z-quarter + 20 KB buffers = 36 KB; 3 CTAs/SM (reg-limited).
// ---------------------------------------------------------------------------
__global__ void __launch_bounds__(256, 3) attn_kernel(const float* __restrict__ x1) {
    extern __shared__ char smem_raw[];
    float4* zs = reinterpret_cast<float4*>(smem_raw);             // 16 KB
    unsigned short* tb = reinterpret_cast<unsigned short*>(smem_raw + 16384);
    const int g       = blockIdx.y;
    const int quarter = blockIdx.z;

    const float4* srcA = g_zA + g * PAIRS + quarter * QPAIRS;
    const float4* srcB = g_zB + g * PAIRS + quarter * QPAIRS;
    for (int i = threadIdx.x; i < QPAIRS; i += 256) {
        zs[i]          = srcA[i];              // linear copy keeps interleave
        zs[QPAIRS + i] = srcB[i];
    }
    __syncthreads();

    const int q     = threadIdx.x & 3;
    const int rslot = threadIdx.x >> 2;                 // 0..63

    int   row[4];
    float a[4], b[4], c[4];
    unsigned long long aa[4], bb[4], cc[4];
    float m[4];
    int   cnt[4];
    unsigned short* buf[4];
#pragma unroll
    for (int r = 0; r < 4; r++) {
        const int s = blockIdx.x * 256 + r * 64 + rslot;
        row[r] = g * SEQ + s;
        a[r] = x1[row[r] * 3 + 0];
        b[r] = x1[row[r] * 3 + 1];
        c[r] = x1[row[r] * 3 + 2];
        aa[r] = pack2(a[r], a[r]);
        bb[r] = pack2(b[r], b[r]);
        cc[r] = pack2(c[r], c[r]);
        m[r] = -3.0e38f;
        cnt[r] = 0;
        buf[r] = tb + threadIdx.x * (4 * CAP) + r * CAP;
    }

    const ulonglong2* ZA = reinterpret_cast<const ulonglong2*>(zs) + q;
    const ulonglong2* ZB = ZA + QPAIRS;

    for (int p = 0; p < 128; p += 4) {         // 8 t's x 4 rows per iteration
        const ulonglong2 A0 = ZA[(p + 0) << 2], B0 = ZB[(p + 0) << 2];
        const ulonglong2 A1 = ZA[(p + 1) << 2], B1 = ZB[(p + 1) << 2];
        const ulonglong2 A2 = ZA[(p + 2) << 2], B2 = ZB[(p + 2) << 2];
        const ulonglong2 A3 = ZA[(p + 3) << 2], B3 = ZB[(p + 3) << 2];

#pragma unroll
        for (int r = 0; r < 4; r++) {
            const unsigned long long R0 =
                fma2(aa[r], A0.x, fma2(bb[r], A0.y, fma2(cc[r], B0.x, B0.y)));
            const unsigned long long R1 =
                fma2(aa[r], A1.x, fma2(bb[r], A1.y, fma2(cc[r], B1.x, B1.y)));
            const unsigned long long R2 =
                fma2(aa[r], A2.x, fma2(bb[r], A2.y, fma2(cc[r], B2.x, B2.y)));
            const unsigned long long R3 =
                fma2(aa[r], A3.x, fma2(bb[r], A3.y, fma2(cc[r], B3.x, B3.y)));
            float s0, s1, s2, s3, s4, s5, s6, s7;
            unpack2(R0, s0, s1); unpack2(R1, s2, s3);
            unpack2(R2, s4, s5); unpack2(R3, s6, s7);
            const float pm = fmaxf(fmaxf(fmaxf(s0, s1), fmaxf(s2, s3)),
                                   fmaxf(fmaxf(s4, s5), fmaxf(s6, s7)));
            if (pm > m[r] - WIN) {             // cold path (rare)
                m[r] = fmaxf(m[r], pm);
                const float sv[8] = {s0, s1, s2, s3, s4, s5, s6, s7};
#pragma unroll
                for (int j = 0; j < 8; j++)
                    if (sv[j] > m[r] - WIN)
                        emit32(buf[r], cnt[r], zs, q, a[r], b[r], c[r],
                               m[r], 2 * p + j);
            }
        }
    }

#pragma unroll
    for (int r = 0; r < 4; r++)
        finalize_row(zs, buf[r], cnt[r], m[r], q, g, quarter, row[r],
                     a[r], b[r], c[r]);
}

// ---------------------------------------------------------------------------
// Merge the four t-quarters per row: exact cross-part softmax combine + output.
// ---------------------------------------------------------------------------
__global__ void merge_kernel(float* __restrict__ out) {
    const int row = blockIdx.x * blockDim.x + threadIdx.x;
    if (row >= NROWS) return;
    const float* p0 = g_part + (size_t)row * 10;
    const float* p1 = g_part + ((size_t)NROWS     + row) * 10;
    const float* p2 = g_part + ((size_t)NROWS * 2 + row) * 10;
    const float* p3 = g_part + ((size_t)NROWS * 3 + row) * 10;
    const float M = fmaxf(fmaxf(p0[8], p1[8]), fmaxf(p2[8], p3[8]));
    const float f0 = __expf(p0[8] - M);
    const float f1 = __expf(p1[8] - M);
    const float f2 = __expf(p2[8] - M);
    const float f3 = __expf(p3[8] - M);
    const float l = fmaf(f0, p0[9], fmaf(f1, p1[9], fmaf(f2, p2[9], f3 * p3[9])));
    const float inv = 2.0f / l;                        // dropout 1/(1-p) = 2
#pragma unroll
    for (int h = 0; h < 8; h++)
        out[(size_t)row * DH + h] =
            fmaf(f0, p0[h], fmaf(f1, p1[h], fmaf(f2, p2[h], f3 * p3[h]))) * inv;
}

// ---------------------------------------------------------------------------
extern "C" void kernel_launch(void* const* d_in, const int* in_sizes, int n_in,
                              void* d_out, int out_size) {
    const float* x1 = (const float*)d_in[0];
    const float* x2 = (const float*)d_in[1];
    const float* Wq = (const float*)d_in[2];
    const float* bq = (const float*)d_in[3];
    const float* Wk = (const float*)d_in[4];
    // d_in[5] = bk: per-row constant -> cancels in softmax
    const float* Wv = (const float*)d_in[6];
    const float* bv = (const float*)d_in[7];
    float* out = (float*)d_out;

    precompute_kernel<<<(NHEAD * SEQ + 255) / 256, 256>>>(x1, x2, Wq, bq, Wk, Wv, bv);

    const int smem = 2 * QPAIRS * (int)sizeof(float4)             // 16 KB z-quarter
                   + 256 * 4 * CAP * (int)sizeof(unsigned short); // 20 KB buffers
    cudaFuncSetAttribute(attn_kernel, cudaFuncAttributeMaxDynamicSharedMemorySize, smem);
    dim3 grid(SEQ / 256, NHEAD, NSPLIT);
    attn_kernel<<<grid, 256, smem>>>(x1);

    merge_kernel<<<(NROWS + 255) / 256, 256>>>(out);
}

// round 14
// speedup vs baseline: 1.8399x; 1.8399x over previous
#include <cuda_runtime.h>

#define NHEAD  8
#define SEQ    4096
#define DH     8
#define PAIRS  2048              // t-pairs per head
#define HPAIRS 1024              // t-pairs per half (split-KV x2)
#define CAP    10                // deferred-entry slots per (thread,row)
#define WIN    20.0f             // window: dropped terms < 4096*e^-20 ~ 8e-6
#define NROWS  (NHEAD * SEQ)

// ---------------- __device__ scratch (no allocations allowed) ----------------
// Keys packed per half, INTERLEAVED inside each half: pair p (0..2047) of head
// g: half = p>>10, ph = p & 1023, dst = g*2048 + half*1024 + (ph&255)*4 + (ph>>8)
// so quad lane q (owning 256 pairs of the half) reads zs[p*4+q]: 64 B contiguous
// per quad + row broadcast -> conflict-free.
//  zA word: (zx_t, zx_t1, zy_t, zy_t1),  zB word: (zz_t, zz_t1, zw_t, zw_t1)
// where z_t = SCALE * ( Wq^T Wk x2_t , bq . Wk x2_t ).
__device__ float4 g_zA[NHEAD * PAIRS];
__device__ float4 g_zB[NHEAD * PAIRS];
__device__ float  g_v [NHEAD * SEQ * DH];    // v[g][t][h] = Wv x1 + bv
// Per (half, row) softmax partials: acc[8], m, l  (10 floats)
__device__ float  g_part[2 * NROWS * 10];

// ---------------------------------------------------------------------------
// Packed f32x2 helpers
// ---------------------------------------------------------------------------
__device__ __forceinline__ unsigned long long fma2(unsigned long long a,
                                                   unsigned long long b,
                                                   unsigned long long c) {
    unsigned long long d;
    asm("fma.rn.f32x2 %0, %1, %2, %3;" : "=l"(d) : "l"(a), "l"(b), "l"(c));
    return d;
}
__device__ __forceinline__ unsigned long long pack2(float x, float y) {
    unsigned long long r;
    asm("mov.b64 %0, {%1, %2};" : "=l"(r) : "f"(x), "f"(y));
    return r;
}
__device__ __forceinline__ void unpack2(unsigned long long v, float& x, float& y) {
    asm("mov.b64 {%0, %1}, %2;" : "=f"(x), "=f"(y) : "l"(v));
}

// ---------------------------------------------------------------------------
// Precompute: ONE THREAD PER t (32768 threads; measured 6.3 us). Pair packing
// via shfl with the neighbor lane (t, t^1 are adjacent lanes).
// ---------------------------------------------------------------------------
__global__ void precompute_kernel(const float* __restrict__ x1,
                                  const float* __restrict__ x2,
                                  const float* __restrict__ Wq,
                                  const float* __restrict__ bq,
                                  const float* __restrict__ Wk,
                                  const float* __restrict__ Wv,
                                  const float* __restrict__ bv) {
    const int i = blockIdx.x * blockDim.x + threadIdx.x;  // i = g*SEQ + t
    if (i >= NHEAD * SEQ) return;
    const int g = i >> 12;
    const int t = i & (SEQ - 1);

    const float SCALEF = 1448.1546878700492f;  // 2^10.5

    float X1[3], X2[3];
#pragma unroll
    for (int j = 0; j < 3; j++) { X1[j] = x1[i * 3 + j]; X2[j] = x2[i * 3 + j]; }

    // z = SCALE * ( Wq^T (Wk x2), bq . (Wk x2) )
    float y0 = 0.f, y1 = 0.f, y2 = 0.f, w = 0.f;
#pragma unroll
    for (int h = 0; h < 8; h++) {
        float u = fmaf(Wk[h * 3 + 0], X2[0],
                  fmaf(Wk[h * 3 + 1], X2[1], Wk[h * 3 + 2] * X2[2]));
        y0 = fmaf(Wq[h * 3 + 0], u, y0);
        y1 = fmaf(Wq[h * 3 + 1], u, y1);
        y2 = fmaf(Wq[h * 3 + 2], u, y2);
        w  = fmaf(bq[h], u, w);
    }
    y0 *= SCALEF; y1 *= SCALEF; y2 *= SCALEF; w *= SCALEF;

    // v row
#pragma unroll
    for (int h = 0; h < 8; h++) {
        g_v[(size_t)i * 8 + h] =
            fmaf(Wv[h * 3 + 0], X1[0], fmaf(Wv[h * 3 + 1], X1[1],
            fmaf(Wv[h * 3 + 2], X1[2], bv[h])));
    }

    // pair packing: even lane gathers partner's (t+1) z components
    const float py0 = __shfl_xor_sync(0xffffffffu, y0, 1);
    const float py1 = __shfl_xor_sync(0xffffffffu, y1, 1);
    const float py2 = __shfl_xor_sync(0xffffffffu, y2, 1);
    const float pw  = __shfl_xor_sync(0xffffffffu, w,  1);
    if (!(t & 1)) {
        const int p  = t >> 1;
        const int ph = p & (HPAIRS - 1);
        const int dst = g * PAIRS + (p >> 10) * HPAIRS + ((ph & 255) << 2) + (ph >> 8);
        g_zA[dst] = make_float4(y0, py0, y1, py1);
        g_zB[dst] = make_float4(y2, py2, w, pw);
    }
}

// ---------------------------------------------------------------------------
// Threefry2x32, partitionable mode: word(i) = x0^x1 of counter (0, i),
// key (0, 42). keep <=> MSB == 0.
// ---------------------------------------------------------------------------
__device__ __forceinline__ unsigned rotl32(unsigned x, int r) {
    return __funnelshift_l(x, x, r);
}
__device__ __forceinline__ unsigned threefry_word(unsigned idx) {
    const unsigned K1 = 42u;
    const unsigned K2 = 0x1BD11BF0u;
    unsigned x0 = 0u;
    unsigned x1 = idx + K1;
#define TF_R(r)  { x0 += x1; x1 = rotl32(x1, r); x1 ^= x0; }
#define TF_G(a,b,c,d,j0,j1) TF_R(a) TF_R(b) TF_R(c) TF_R(d) x0 += (j0); x1 += (j1);
    TF_G(13, 15, 26,  6, K1,       K2 + 1u)
    TF_G(17, 29, 16, 24, K2,       0u + 2u)
    TF_G(13, 15, 26,  6, 0u,       K1 + 3u)
    TF_G(17, 29, 16, 24, K1,       K2 + 4u)
    TF_G(13, 15, 26,  6, K2,       0u + 5u)
#undef TF_G
#undef TF_R
    return x0 ^ x1;
}

// Exact fp32 re-score of lane-local t (0..511) from smem (same FMA chain as
// the scan -> bit-identical values).
__device__ __forceinline__ float score_at(const float4* __restrict__ zs, int q,
                                          int tloc, float a, float b, float c) {
    const int idx = ((tloc >> 1) << 2) + q;
    const float4 A = zs[idx];
    const float4 B = zs[HPAIRS + idx];
    const bool odd = (tloc & 1);
    const float zx = odd ? A.y : A.x;
    const float zy = odd ? A.w : A.z;
    const float zz = odd ? B.y : B.x;
    const float zw = odd ? B.w : B.z;
    return fmaf(a, zx, fmaf(b, zy, fmaf(c, zz, zw)));
}

__device__ __forceinline__ void emit32(unsigned short* buf, int& cnt,
                                       const float4* __restrict__ zs, int q,
                                       float a, float b, float c,
                                       float m, int tl) {
    if (cnt == CAP) {                       // prune entries below current window
        int k = 0;
        for (int i = 0; i < CAP; i++) {
            const int t2 = buf[i];
            if (score_at(zs, q, t2, a, b, c) > m - WIN)
                buf[k++] = (unsigned short)t2;
        }
        cnt = k;
        if (cnt == CAP) cnt = CAP - 1;      // ~impossible; keep newest
    }
    buf[cnt++] = (unsigned short)tl;
}

// Phase 2 + quad merge; writes (acc[8], m, l) partial for (half, row).
__device__ __forceinline__ void finalize_row(const float4* __restrict__ zs,
                                             const unsigned short* buf, int cnt,
                                             float m, int q, int g, int half,
                                             int row, float a, float b, float c) {
    const int tbase = half * 2048 + (q << 9);          // global t of lane's range
    const float* vg = g_v + ((size_t)g * SEQ + tbase) * DH;
    const unsigned rowbase = ((unsigned)row << 12) + (unsigned)tbase;
    const float M = m;
    float l = 0.f;
    float acc0 = 0.f, acc1 = 0.f, acc2 = 0.f, acc3 = 0.f;
    float acc4 = 0.f, acc5 = 0.f, acc6 = 0.f, acc7 = 0.f;
    for (int i = 0; i < cnt; i++) {
        const int tloc = buf[i];
        const float sc = score_at(zs, q, tloc, a, b, c);
        if (sc > M - WIN) {
            const float e = __expf(sc - M);
            l += e;                                    // denominator: mask-free
            const unsigned w = threefry_word(rowbase + (unsigned)tloc);
            if (!(w & 0x80000000u)) {                  // keep (u < 0.5)
                const float4* vp =
                    reinterpret_cast<const float4*>(vg + (size_t)tloc * DH);
                const float4 va = vp[0];
                const float4 vb = vp[1];
                acc0 = fmaf(e, va.x, acc0);
                acc1 = fmaf(e, va.y, acc1);
                acc2 = fmaf(e, va.z, acc2);
                acc3 = fmaf(e, va.w, acc3);
                acc4 = fmaf(e, vb.x, acc4);
                acc5 = fmaf(e, vb.y, acc5);
                acc6 = fmaf(e, vb.z, acc6);
                acc7 = fmaf(e, vb.w, acc7);
            }
        }
    }
    // quad merge (lanes xor 1, 2 share a row)
    float Mq = M;
    Mq = fmaxf(Mq, __shfl_xor_sync(0xffffffffu, Mq, 1));
    Mq = fmaxf(Mq, __shfl_xor_sync(0xffffffffu, Mq, 2));
    const float f = __expf(M - Mq);
    l *= f;
    acc0 *= f; acc1 *= f; acc2 *= f; acc3 *= f;
    acc4 *= f; acc5 *= f; acc6 *= f; acc7 *= f;
#pragma unroll
    for (int d = 1; d <= 2; d <<= 1) {
        l    += __shfl_xor_sync(0xffffffffu, l,    d);
        acc0 += __shfl_xor_sync(0xffffffffu, acc0, d);
        acc1 += __shfl_xor_sync(0xffffffffu, acc1, d);
        acc2 += __shfl_xor_sync(0xffffffffu, acc2, d);
        acc3 += __shfl_xor_sync(0xffffffffu, acc3, d);
        acc4 += __shfl_xor_sync(0xffffffffu, acc4, d);
        acc5 += __shfl_xor_sync(0xffffffffu, acc5, d);
        acc6 += __shfl_xor_sync(0xffffffffu, acc6, d);
        acc7 += __shfl_xor_sync(0xffffffffu, acc7, d);
    }
    float* part = g_part + ((size_t)half * NROWS + row) * 10;
    const float oc[8] = {acc0, acc1, acc2, acc3, acc4, acc5, acc6, acc7};
    part[2 * q]     = oc[2 * q];
    part[2 * q + 1] = oc[2 * q + 1];
    if (q == 0) { part[8] = Mq; part[9] = l; }
}

// ---------------------------------------------------------------------------
// Main kernel. Grid (SEQ/128, NHEAD, 2); block = 256 threads: 64 row-slots x
// quad(4). Each thread owns TWO rows (s0, s0+64). blockIdx.z = t-half; quad
// lane q scans the half's pairs [q*256,(q+1)*256) (512 t's, 64 iterations).
// smem = 32 KB z-half + 10 KB buffers.
// ---------------------------------------------------------------------------
__global__ void __launch_bounds__(256) attn_kernel(const float* __restrict__ x1) {
    extern __shared__ char smem_raw[];
    float4* zs = reinterpret_cast<float4*>(smem_raw);             // 32 KB
    unsigned short* tb = reinterpret_cast<unsigned short*>(smem_raw + 32768);
    const int g    = blockIdx.y;
    const int half = blockIdx.z;

    const float4* srcA = g_zA + g * PAIRS + half * HPAIRS;
    const float4* srcB = g_zB + g * PAIRS + half * HPAIRS;
    for (int i = threadIdx.x; i < HPAIRS; i += 256) {
        zs[i]          = srcA[i];              // linear copy keeps interleave
        zs[HPAIRS + i] = srcB[i];
    }
    __syncthreads();

    const int q     = threadIdx.x & 3;
    const int rslot = threadIdx.x >> 2;                 // 0..63
    const int s0    = blockIdx.x * 128 + rslot;
    const int s1    = s0 + 64;
    const int row0  = g * SEQ + s0;
    const int row1  = g * SEQ + s1;

    const float a0 = x1[row0 * 3 + 0], b0 = x1[row0 * 3 + 1], c0 = x1[row0 * 3 + 2];
    const float a1 = x1[row1 * 3 + 0], b1 = x1[row1 * 3 + 1], c1 = x1[row1 * 3 + 2];
    const unsigned long long aa0 = pack2(a0, a0), bb0 = pack2(b0, b0), cc0 = pack2(c0, c0);
    const unsigned long long aa1 = pack2(a1, a1), bb1 = pack2(b1, b1), cc1 = pack2(c1, c1);

    unsigned short* buf0 = tb + threadIdx.x * (2 * CAP);
    unsigned short* buf1 = buf0 + CAP;
    int cnt0 = 0, cnt1 = 0;

    const ulonglong2* ZA = reinterpret_cast<const ulonglong2*>(zs) + q;
    const ulonglong2* ZB = ZA + HPAIRS;

    float m0 = -3.0e38f, m1 = -3.0e38f;

    for (int p = 0; p < 256; p += 4) {         // 8 t's x 2 rows per iteration
        const ulonglong2 A0 = ZA[(p + 0) << 2], B0 = ZB[(p + 0) << 2];
        const ulonglong2 A1 = ZA[(p + 1) << 2], B1 = ZB[(p + 1) << 2];
        const ulonglong2 A2 = ZA[(p + 2) << 2], B2 = ZB[(p + 2) << 2];
        const ulonglong2 A3 = ZA[(p + 3) << 2], B3 = ZB[(p + 3) << 2];

        const unsigned long long R00 = fma2(aa0, A0.x, fma2(bb0, A0.y, fma2(cc0, B0.x, B0.y)));
        const unsigned long long R01 = fma2(aa0, A1.x, fma2(bb0, A1.y, fma2(cc0, B1.x, B1.y)));
        const unsigned long long R02 = fma2(aa0, A2.x, fma2(bb0, A2.y, fma2(cc0, B2.x, B2.y)));
        const unsigned long long R03 = fma2(aa0, A3.x, fma2(bb0, A3.y, fma2(cc0, B3.x, B3.y)));
        const unsigned long long R10 = fma2(aa1, A0.x, fma2(bb1, A0.y, fma2(cc1, B0.x, B0.y)));
        const unsigned long long R11 = fma2(aa1, A1.x, fma2(bb1, A1.y, fma2(cc1, B1.x, B1.y)));
        const unsigned long long R12 = fma2(aa1, A2.x, fma2(bb1, A2.y, fma2(cc1, B2.x, B2.y)));
        const unsigned long long R13 = fma2(aa1, A3.x, fma2(bb1, A3.y, fma2(cc1, B3.x, B3.y)));

        float u0, u1, u2, u3, u4, u5, u6, u7;
        unpack2(R00, u0, u1); unpack2(R01, u2, u3);
        unpack2(R02, u4, u5); unpack2(R03, u6, u7);
        const float pm0 = fmaxf(fmaxf(fmaxf(u0, u1), fmaxf(u2, u3)),
                                fmaxf(fmaxf(u4, u5), fmaxf(u6, u7)));

        float w0, w1, w2, w3, w4, w5, w6, w7;
        unpack2(R10, w0, w1); unpack2(R11, w2, w3);
        unpack2(R12, w4, w5); unpack2(R13, w6, w7);
        const float pm1 = fmaxf(fmaxf(fmaxf(w0, w1), fmaxf(w2, w3)),
                                fmaxf(fmaxf(w4, w5), fmaxf(w6, w7)));

        if (pm0 > m0 - WIN) {                  // cold path row 0
            m0 = fmaxf(m0, pm0);
            const float sv[8] = {u0, u1, u2, u3, u4, u5, u6, u7};
#pragma unroll
            for (int j = 0; j < 8; j++)
                if (sv[j] > m0 - WIN)
                    emit32(buf0, cnt0, zs, q, a0, b0, c0, m0, 2 * p + j);
        }
        if (pm1 > m1 - WIN) {                  // cold path row 1
            m1 = fmaxf(m1, pm1);
            const float sv[8] = {w0, w1, w2, w3, w4, w5, w6, w7};
#pragma unroll
            for (int j = 0; j < 8; j++)
                if (sv[j] > m1 - WIN)
                    emit32(buf1, cnt1, zs, q, a1, b1, c1, m1, 2 * p + j);
        }
    }

    finalize_row(zs, buf0, cnt0, m0, q, g, half, row0, a0, b0, c0);
    finalize_row(zs, buf1, cnt1, m1, q, g, half, row1, a1, b1, c1);
}

// ---------------------------------------------------------------------------
// Merge the two t-halves per row: exact cross-half softmax combine + output.
// ---------------------------------------------------------------------------
__global__ void merge_kernel(float* __restrict__ out) {
    const int row = blockIdx.x * blockDim.x + threadIdx.x;
    if (row >= NROWS) return;
    const float* p0 = g_part + (size_t)row * 10;
    const float* p1 = g_part + ((size_t)NROWS + row) * 10;
    const float m0 = p0[8], l0 = p0[9];
    const float m1 = p1[8], l1 = p1[9];
    const float M  = fmaxf(m0, m1);
    const float f0 = __expf(m0 - M);
    const float f1 = __expf(m1 - M);
    const float l  = fmaf(f0, l0, f1 * l1);
    const float inv = 2.0f / l;                        // dropout 1/(1-p) = 2
#pragma unroll
    for (int h = 0; h < 8; h++)
        out[(size_t)row * DH + h] = fmaf(f0, p0[h], f1 * p1[h]) * inv;
}

// ---------------------------------------------------------------------------
extern "C" void kernel_launch(void* const* d_in, const int* in_sizes, int n_in,
                              void* d_out, int out_size) {
    const float* x1 = (const float*)d_in[0];
    const float* x2 = (const float*)d_in[1];
    const float* Wq = (const float*)d_in[2];
    const float* bq = (const float*)d_in[3];
    const float* Wk = (const float*)d_in[4];
    // d_in[5] = bk: per-row constant -> cancels in softmax
    const float* Wv = (const float*)d_in[6];
    const float* bv = (const float*)d_in[7];
    float* out = (float*)d_out;

    precompute_kernel<<<(NHEAD * SEQ + 255) / 256, 256>>>(x1, x2, Wq, bq, Wk, Wv, bv);

    const int smem = 2 * HPAIRS * (int)sizeof(float4)             // 32 KB z-half
                   + 256 * 2 * CAP * (int)sizeof(unsigned short); // 10 KB buffers
    cudaFuncSetAttribute(attn_kernel, cudaFuncAttributeMaxDynamicSharedMemorySize, smem);
    dim3 grid(SEQ / 128, NHEAD, 2);
    attn_kernel<<<grid, 256, smem>>>(x1);

    merge_kernel<<<(NROWS + 255) / 256, 256>>>(out);
}